// round 14
// baseline (speedup 1.0000x reference)
#include <cuda_runtime.h>
#include <cuda_fp16.h>
#include <cstdint>

// ---------------------------------------------------------------------------
// Persistent fused 2-layer LSTM, fp16 tensor cores, FUSED cell update.
// 512 threads / 16 warps per CTA, split into TWO independent halves:
//   warps 0-7  <-> rows  0-31   (named barrier 1)
//   warps 8-15 <-> rows 32-63   (named barrier 2)
// The halves run the recurrence independently and drift out of phase, so one
// half's MMA stream covers the other half's epilogue/barrier windows on every
// SMSP. Each warp: 2 jb passes (unified 2*KT k-stream, ring-3 B prefetch),
// mt=2 row tiles, fused LSTM cell epilogue in registers.
// ---------------------------------------------------------------------------

#define NT      512
#define BTILE   64
#define HROWS   32
#define NCTA    128
#define TSTEPS  28
#define HIDN    128
#define GATES   512
#define KT0     10          // K=160 (32-padded x | h0) / 16
#define KT1     16          // K=256 (h1 | h0) / 16
#define SA0_S   168         // halves per row
#define SA1_S   264

#define A0_HALVES (64*SA0_S)                 // 10752 per buffer
#define A1_HALVES (64*SA1_S)                 // 16896 per buffer

#define OFF_A0   0
#define OFF_A1   (OFF_A0 + 2*A0_HALVES*2)    // 43008
#define OFF_C0   (OFF_A1 + 2*A1_HALVES*2)    // 110592
#define OFF_C1   (OFF_C0 + 16*512*4)         // 143360
#define OFF_B0   (OFF_C1 + 16*512*4)         // 176128
#define OFF_B1   (OFF_B0 + GATES*4)          // 178176
#define SMEM_BYTES (OFF_B1 + GATES*4)        // 180224

// fragment-packed weights: [jb(16)][gate(4)][kt][lane(32)] -> linear = tid order
__device__ __align__(16) uint2 g_Wf0[16*4*KT0*32];
__device__ __align__(16) uint2 g_Wf1[16*4*KT1*32];
__device__ float g_bias0[GATES];
__device__ float g_bias1[GATES];

// ---------------------------------------------------------------------------
__device__ __forceinline__ __half2 lh2tanh(__half2 x) {
    __half2 y;
    asm("tanh.approx.f16x2 %0, %1;" : "=r"(*(uint32_t*)&y) : "r"(*(uint32_t*)&x));
    return y;
}

__device__ __forceinline__ void ldsm4(uint32_t* r, uint32_t addr) {
    asm volatile("ldmatrix.sync.aligned.m8n8.x4.shared.b16 {%0,%1,%2,%3}, [%4];"
                 : "=r"(r[0]), "=r"(r[1]), "=r"(r[2]), "=r"(r[3]) : "r"(addr));
}

__device__ __forceinline__ void mma16816(float* c, const uint32_t* a, const uint32_t* b) {
    asm volatile("mma.sync.aligned.m16n8k16.row.col.f32.f16.f16.f32 "
                 "{%0,%1,%2,%3}, {%4,%5,%6,%7}, {%8,%9}, {%0,%1,%2,%3};"
                 : "+f"(c[0]), "+f"(c[1]), "+f"(c[2]), "+f"(c[3])
                 : "r"(a[0]), "r"(a[1]), "r"(a[2]), "r"(a[3]), "r"(b[0]), "r"(b[1]));
}

__device__ __forceinline__ void barhalf(int id) {
    asm volatile("bar.sync %0, %1;" :: "r"(id), "r"(256) : "memory");
}

__device__ __forceinline__ uint32_t pack2(float a, float b) {
    __half2 h = __floats2half2_rn(a, b);
    return *reinterpret_cast<uint32_t*>(&h);
}

// ---------------------------------------------------------------------------
// Prep: pack weights into gate-major fragment layout + fuse biases.
// Global column n = gate*128 + jb*8 + (lane>>2); k = kt*16 + (lane&3)*2.
// W0[n][k]: k<28 -> w_ih0, 28..31 -> 0, 32..159 -> w_hh0[k-32]
// W1[n][k]: k<128 -> w_hh1, else w_ih1[k-128]
// ---------------------------------------------------------------------------
__device__ __forceinline__ float w0val(const float* wih0, const float* whh0, int n, int k) {
    if (k < 28)  return wih0[n*28 + k];
    if (k < 32)  return 0.0f;
    return whh0[n*HIDN + (k - 32)];
}
__device__ __forceinline__ float w1val(const float* wih1, const float* whh1, int n, int k) {
    if (k < HIDN) return whh1[n*HIDN + k];
    return wih1[n*HIDN + (k - HIDN)];
}

__global__ void prep_kernel(const float* __restrict__ wih0, const float* __restrict__ whh0,
                            const float* __restrict__ bih0, const float* __restrict__ bhh0,
                            const float* __restrict__ wih1, const float* __restrict__ whh1,
                            const float* __restrict__ bih1, const float* __restrict__ bhh1) {
    int tid = blockIdx.x * blockDim.x + threadIdx.x;
    if (tid < GATES) {
        g_bias0[tid] = bih0[tid] + bhh0[tid];
        g_bias1[tid] = bih1[tid] + bhh1[tid];
    }
    if (tid < 16*4*KT0*32) {
        int lane = tid & 31;
        int kt   = (tid >> 5) % KT0;
        int r    = tid / (32*KT0);
        int gate = r & 3, jb = r >> 2;
        int n = gate*128 + jb*8 + (lane >> 2);
        int k = kt*16 + (lane & 3)*2;
        uint2 u;
        u.x = pack2(w0val(wih0, whh0, n, k),   w0val(wih0, whh0, n, k+1));
        u.y = pack2(w0val(wih0, whh0, n, k+8), w0val(wih0, whh0, n, k+9));
        g_Wf0[tid] = u;
    }
    if (tid < 16*4*KT1*32) {
        int lane = tid & 31;
        int kt   = (tid >> 5) % KT1;
        int r    = tid / (32*KT1);
        int gate = r & 3, jb = r >> 2;
        int n = gate*128 + jb*8 + (lane >> 2);
        int k = kt*16 + (lane & 3)*2;
        uint2 u;
        u.x = pack2(w1val(wih1, whh1, n, k),   w1val(wih1, whh1, n, k+1));
        u.y = pack2(w1val(wih1, whh1, n, k+8), w1val(wih1, whh1, n, k+9));
        g_Wf1[tid] = u;
    }
}

// ---------------------------------------------------------------------------
// Fused LSTM epilogue for one pass (mt=2 row tiles, 8 j columns).
// sB: biases, 0.5-prescaled for i/f/o gates, raw for g.
// cW: per-warp c slice (16 cells x 32 lanes); cbase = pass*8.
// ---------------------------------------------------------------------------
template<bool DUAL>
__device__ __forceinline__ void lstm_epilogue(
    float (&acc)[2][4][4], const float* __restrict__ sB, float* __restrict__ cW,
    int cbase, int jb, int rowbase,
    half* __restrict__ dA, int strA, int offA,
    half* __restrict__ dB, int strB, int offB, int lane)
{
    const int j0 = jb*8 + (lane & 3)*2;
    const float2 bI = *(const float2*)&sB[        j0];
    const float2 bF = *(const float2*)&sB[128   + j0];
    const float2 bG = *(const float2*)&sB[256   + j0];
    const float2 bO = *(const float2*)&sB[384   + j0];
    const __half2 H05 = __float2half2_rn(0.5f);
#pragma unroll
    for (int mt = 0; mt < 2; ++mt) {
        const int r0 = rowbase + mt*16 + (lane >> 2);
#pragma unroll
        for (int hq = 0; hq < 2; ++hq) {
            const int row = r0 + hq*8;
            const float aI0 = acc[mt][0][2*hq], aI1 = acc[mt][0][2*hq+1];
            const float aF0 = acc[mt][1][2*hq], aF1 = acc[mt][1][2*hq+1];
            const float aG0 = acc[mt][2][2*hq], aG1 = acc[mt][2][2*hq+1];
            const float aO0 = acc[mt][3][2*hq], aO1 = acc[mt][3][2*hq+1];
            // sigmoid(x) = 0.5*tanh(0.5x)+0.5 ; biases prescaled by 0.5 for i/f/o
            __half2 TI = lh2tanh(__floats2half2_rn(fmaf(aI0,0.5f,bI.x), fmaf(aI1,0.5f,bI.y)));
            __half2 TF = lh2tanh(__floats2half2_rn(fmaf(aF0,0.5f,bF.x), fmaf(aF1,0.5f,bF.y)));
            __half2 TG = lh2tanh(__floats2half2_rn(aG0 + bG.x,          aG1 + bG.y));
            __half2 TO = lh2tanh(__floats2half2_rn(fmaf(aO0,0.5f,bO.x), fmaf(aO1,0.5f,bO.y)));
            __half2 SI = __hfma2(TI, H05, H05);
            __half2 SF = __hfma2(TF, H05, H05);
            __half2 SO = __hfma2(TO, H05, H05);
            float2 fI = __half22float2(SI);
            float2 fF = __half22float2(SF);
            float2 fG = __half22float2(TG);
            const int ci = cbase + mt*4 + hq*2;
            float c0 = cW[ci*32 + lane];
            float c1 = cW[(ci+1)*32 + lane];
            c0 = fmaf(fF.x, c0, fI.x * fG.x);
            c1 = fmaf(fF.y, c1, fI.y * fG.y);
            cW[ci*32 + lane]     = c0;
            cW[(ci+1)*32 + lane] = c1;
            __half2 H = __hmul2(SO, lh2tanh(__floats2half2_rn(c0, c1)));
            *(__half2*)&dA[row*strA + offA + j0] = H;
            if (DUAL) *(__half2*)&dB[row*strB + offB + j0] = H;
        }
    }
}

// ---------------------------------------------------------------------------
// One layer for one half: unified 2-pass k-stream (u in [0, 2*KT)), ring-3 B
// prefetch crossing the pass boundary, epilogue per pass. The half's named
// barrier sits AFTER the first B prefetches (hides L2 latency).
// ---------------------------------------------------------------------------
template<int KT, int SAS, bool DUAL>
__device__ __forceinline__ void gemm_layer(
    const half* __restrict__ sA, const uint2* __restrict__ Wf,
    const float* __restrict__ sB, float* __restrict__ cW,
    half* __restrict__ dA, int strA, int offA,
    half* __restrict__ dB, int strB, int offB,
    int rowbase, int barid, int hwarp, int lane)
{
    const uint32_t aBase = (uint32_t)__cvta_generic_to_shared(sA)
                         + (uint32_t)(rowbase*SAS*2);
    const int lrow  = lane & 15;
    const int lkoff = (lane >> 4) * 8;
    const uint2* W0 = Wf + (size_t)((hwarp    )*4*KT)*32 + lane;
    const uint2* W1 = Wf + (size_t)((hwarp + 8)*4*KT)*32 + lane;

    uint32_t breg[3][4][2];
    uint32_t areg[2][4];
    float acc[2][4][4];

    auto loadB = [&](int u) {
        const uint2* p = (u >= KT) ? W1 : W0;
        const int kt   = (u >= KT) ? u - KT : u;
        const int slot = u % 3;
#pragma unroll
        for (int s = 0; s < 4; ++s) {
            uint2 v = p[(s*KT + kt)*32];
            breg[slot][s][0] = v.x;
            breg[slot][s][1] = v.y;
        }
    };

    loadB(0); loadB(1);
    barhalf(barid);                // covers this half's producer writes

#pragma unroll
    for (int mt = 0; mt < 2; ++mt)
#pragma unroll
        for (int s = 0; s < 4; ++s)
#pragma unroll
            for (int q = 0; q < 4; ++q) acc[mt][s][q] = 0.0f;

#pragma unroll
    for (int u = 0; u < 2*KT; ++u) {
        const int kt = (u >= KT) ? u - KT : u;
#pragma unroll
        for (int mt = 0; mt < 2; ++mt)
            ldsm4(areg[mt],
                  aBase + (uint32_t)(((mt*16 + lrow)*SAS + kt*16 + lkoff) * 2));
        if (u + 2 < 2*KT) loadB(u + 2);   // (u+2)%3 != u%3, != (u+1)%3
#pragma unroll
        for (int mt = 0; mt < 2; ++mt)
#pragma unroll
            for (int s = 0; s < 4; ++s)
                mma16816(acc[mt][s], areg[mt], breg[u % 3][s]);
        if (u == KT - 1) {
            lstm_epilogue<DUAL>(acc, sB, cW, 0, hwarp, rowbase,
                                dA, strA, offA, dB, strB, offB, lane);
#pragma unroll
            for (int mt = 0; mt < 2; ++mt)
#pragma unroll
                for (int s = 0; s < 4; ++s)
#pragma unroll
                    for (int q = 0; q < 4; ++q) acc[mt][s][q] = 0.0f;
        }
    }
    lstm_epilogue<DUAL>(acc, sB, cW, 8, hwarp + 8, rowbase,
                        dA, strA, offA, dB, strB, offB, lane);
}

// ---------------------------------------------------------------------------
__global__ __launch_bounds__(NT, 1)
void lstm_kernel(const float* __restrict__ x, const float* __restrict__ w_out,
                 const float* __restrict__ b_out, float* __restrict__ out) {
    extern __shared__ char smem[];
    half*  A0 = (half*)(smem + OFF_A0);   // 2 buffers [64][168]: 0..31 x(+pad), 32..159 h0
    half*  A1 = (half*)(smem + OFF_A1);   // 2 buffers [64][264]: 0..127 h1, 128..255 h0
    float* C0 = (float*)(smem + OFF_C0);  // [warp][cell(16)][lane]
    float* C1 = (float*)(smem + OFF_C1);
    float* sB0 = (float*)(smem + OFF_B0);
    float* sB1 = (float*)(smem + OFF_B1);

    const int tid   = threadIdx.x;
    const int warp  = tid >> 5;
    const int lane  = tid & 31;
    const int half_ = warp >> 3;          // 0 or 1
    const int hwarp = warp & 7;
    const int htid  = tid & 255;
    const int rowbase = half_ * HROWS;
    const int barid   = 1 + half_;
    float* c0W = C0 + warp*512;
    float* c1W = C1 + warp*512;

    // init: zero states + x pad, scaled biases (cross-half, full sync below)
    for (int i = tid; i < 2*A0_HALVES; i += NT) ((unsigned short*)A0)[i] = 0;
    for (int i = tid; i < 2*A1_HALVES; i += NT) ((unsigned short*)A1)[i] = 0;
    for (int i = tid; i < 16*512; i += NT) { C0[i] = 0.0f; C1[i] = 0.0f; }
    for (int i = tid; i < GATES; i += NT) {
        float b0 = g_bias0[i], b1 = g_bias1[i];
        bool gg = ((i >> 7) == 2);
        sB0[i] = gg ? b0 : 0.5f*b0;
        sB1[i] = gg ? b1 : 0.5f*b1;
    }

    const float* xb = x + (size_t)blockIdx.x * BTILE * 784;

    half* a0r = A0;             half* a0w = A0 + A0_HALVES;
    half* a1r = A1;             half* a1w = A1 + A1_HALVES;

    // x(0) into the first read buffer (full-width; full sync below)
    for (int i = tid; i < BTILE*28; i += NT) {
        int r = i / 28, c = i - r*28;
        a0r[r*SA0_S + c] = __float2half(xb[(size_t)r*784 + 0*28 + c]);
    }
    __syncthreads();

    for (int t = 0; t < TSTEPS; ++t) {
        // layer 0: reads a0r; writes h0 -> a0w (cols 32..) and a1r (cols 128..)
        gemm_layer<KT0, SA0_S, true>(a0r, g_Wf0, sB0, c0W,
                                     a0w, SA0_S, 32, a1r, SA1_S, 128,
                                     rowbase, barid, hwarp, lane);
        // stage this half's x(t+1) into a0w (no reader until next layer-0 bar)
        if (t + 1 < TSTEPS) {
            for (int i = htid; i < HROWS*28; i += 256) {
                int r = i / 28, c = i - r*28;
                int row = rowbase + r;
                a0w[row*SA0_S + c] = __float2half(xb[(size_t)row*784 + (t+1)*28 + c]);
            }
        }
        // layer 1: reads a1r; writes h1 -> a1w (cols 0..127)
        gemm_layer<KT1, SA1_S, false>(a1r, g_Wf1, sB1, c1W,
                                      a1w, SA1_S, 0, (half*)0, 0, 0,
                                      rowbase, barid, hwarp, lane);
        half* tmp;
        tmp = a0r; a0r = a0w; a0w = tmp;
        tmp = a1r; a1r = a1w; a1w = tmp;
    }
    barhalf(barid);

    // output head: out[n][o] = h1_final . w_out[o] + b_out[o]  (own half rows)
    const size_t ng0 = (size_t)blockIdx.x * BTILE;
    for (int i = htid; i < HROWS*10; i += 256) {
        int r = i / 10, o = i - r*10;
        int n = rowbase + r;
        float s = b_out[o];
        const half* hr = a1r + (size_t)n*SA1_S;
#pragma unroll 8
        for (int j = 0; j < HIDN; ++j)
            s = fmaf(__half2float(hr[j]), w_out[o*HIDN + j], s);
        out[(ng0 + n)*10 + o] = s;
    }
}

// ---------------------------------------------------------------------------
extern "C" void kernel_launch(void* const* d_in, const int* in_sizes, int n_in,
                              void* d_out, int out_size) {
    const float* x     = (const float*)d_in[0];
    const float* wih0  = (const float*)d_in[1];
    const float* whh0  = (const float*)d_in[2];
    const float* bih0  = (const float*)d_in[3];
    const float* bhh0  = (const float*)d_in[4];
    const float* wih1  = (const float*)d_in[5];
    const float* whh1  = (const float*)d_in[6];
    const float* bih1  = (const float*)d_in[7];
    const float* bhh1  = (const float*)d_in[8];
    const float* w_out = (const float*)d_in[9];
    const float* b_out = (const float*)d_in[10];

    cudaFuncSetAttribute(lstm_kernel, cudaFuncAttributeMaxDynamicSharedMemorySize, SMEM_BYTES);

    prep_kernel<<<128, 256>>>(wih0, whh0, bih0, bhh0, wih1, whh1, bih1, bhh1);
    lstm_kernel<<<NCTA, NT, SMEM_BYTES>>>(x, w_out, b_out, (float*)d_out);
}

// round 15
// speedup vs baseline: 1.0084x; 1.0084x over previous
#include <cuda_runtime.h>
#include <cuda_fp16.h>
#include <cstdint>

// ---------------------------------------------------------------------------
// Persistent fused 2-layer LSTM, fp16 tensor cores, FUSED cell update,
// CROSS-LAYER phase fusion: layer1(t) and layer0(t+1) are independent, so one
// barrier phase runs a unified 26-kt MMA stream {W1 | W0} with the L1 epilogue
// embedded mid-stream. Barriers: 2/step -> ~1/step. Weights as uint4 packs
// (2x LDG.128 per kt). 16 warps, warp = jb tile, mt=4 row tiles.
// ---------------------------------------------------------------------------

#define NT      512
#define BTILE   64
#define NCTA    128
#define TSTEPS  28
#define HIDN    128
#define GATES   512
#define KT0     10          // K=160 (32-padded x | h0) / 16
#define KT1     16          // K=256 (h1 | h0) / 16
#define KTP     (KT1+KT0)   // 26: unified phase stream
#define SA0_S   168         // halves per row
#define SA1_S   264

#define A0_HALVES (64*SA0_S)                 // 10752 per buffer
#define A1_HALVES (64*SA1_S)                 // 16896 per buffer

#define OFF_A0   0
#define OFF_A1   (OFF_A0 + 2*A0_HALVES*2)    // 43008
#define OFF_C0   (OFF_A1 + 2*A1_HALVES*2)    // 110592
#define OFF_C1   (OFF_C0 + 16*512*4)         // 143360
#define OFF_B0   (OFF_C1 + 16*512*4)         // 176128
#define OFF_B1   (OFF_B0 + GATES*4)          // 178176
#define SMEM_BYTES (OFF_B1 + GATES*4)        // 180224

// uint4-packed weights: [jb(16)][kt][lane(32)][2]; q=0 -> gates 0,1 ; q=1 -> 2,3
__device__ __align__(16) uint4 g_W0q[16*KT0*64];
__device__ __align__(16) uint4 g_W1q[16*KT1*64];
__device__ float g_bias0[GATES];
__device__ float g_bias1[GATES];

// ---------------------------------------------------------------------------
__device__ __forceinline__ __half2 lh2tanh(__half2 x) {
    __half2 y;
    asm("tanh.approx.f16x2 %0, %1;" : "=r"(*(uint32_t*)&y) : "r"(*(uint32_t*)&x));
    return y;
}

__device__ __forceinline__ void ldsm4(uint32_t* r, uint32_t addr) {
    asm volatile("ldmatrix.sync.aligned.m8n8.x4.shared.b16 {%0,%1,%2,%3}, [%4];"
                 : "=r"(r[0]), "=r"(r[1]), "=r"(r[2]), "=r"(r[3]) : "r"(addr));
}

__device__ __forceinline__ void mma16816(float* c, const uint32_t* a, const uint32_t* b) {
    asm volatile("mma.sync.aligned.m16n8k16.row.col.f32.f16.f16.f32 "
                 "{%0,%1,%2,%3}, {%4,%5,%6,%7}, {%8,%9}, {%0,%1,%2,%3};"
                 : "+f"(c[0]), "+f"(c[1]), "+f"(c[2]), "+f"(c[3])
                 : "r"(a[0]), "r"(a[1]), "r"(a[2]), "r"(a[3]), "r"(b[0]), "r"(b[1]));
}

__device__ __forceinline__ uint32_t pack2(float a, float b) {
    __half2 h = __floats2half2_rn(a, b);
    return *reinterpret_cast<uint32_t*>(&h);
}

// ---------------------------------------------------------------------------
// Prep: pack weights into gate-major uint4 fragment layout + fuse biases.
// Column n = gate*128 + jb*8 + (lane>>2); k = kt*16 + (lane&3)*2.
// W0[n][k]: k<28 -> w_ih0, 28..31 -> 0, 32..159 -> w_hh0[k-32]
// W1[n][k]: k<128 -> w_hh1, else w_ih1[k-128]
// ---------------------------------------------------------------------------
__device__ __forceinline__ float w0val(const float* wih0, const float* whh0, int n, int k) {
    if (k < 28)  return wih0[n*28 + k];
    if (k < 32)  return 0.0f;
    return whh0[n*HIDN + (k - 32)];
}
__device__ __forceinline__ float w1val(const float* wih1, const float* whh1, int n, int k) {
    if (k < HIDN) return whh1[n*HIDN + k];
    return wih1[n*HIDN + (k - HIDN)];
}

__global__ void prep_kernel(const float* __restrict__ wih0, const float* __restrict__ whh0,
                            const float* __restrict__ bih0, const float* __restrict__ bhh0,
                            const float* __restrict__ wih1, const float* __restrict__ whh1,
                            const float* __restrict__ bih1, const float* __restrict__ bhh1) {
    int tid = blockIdx.x * blockDim.x + threadIdx.x;
    if (tid < GATES) {
        g_bias0[tid] = bih0[tid] + bhh0[tid];
        g_bias1[tid] = bih1[tid] + bhh1[tid];
    }
    if (tid < 16*KT0*64) {
        int q = tid & 1, r = tid >> 1;
        int lane = r & 31, r2 = r >> 5;
        int kt = r2 % KT0, jb = r2 / KT0;
        int k = kt*16 + (lane & 3)*2;
        int g0 = q*2, g1 = q*2 + 1;
        int n0 = g0*128 + jb*8 + (lane >> 2);
        int n1 = g1*128 + jb*8 + (lane >> 2);
        uint4 u;
        u.x = pack2(w0val(wih0, whh0, n0, k),   w0val(wih0, whh0, n0, k+1));
        u.y = pack2(w0val(wih0, whh0, n0, k+8), w0val(wih0, whh0, n0, k+9));
        u.z = pack2(w0val(wih0, whh0, n1, k),   w0val(wih0, whh0, n1, k+1));
        u.w = pack2(w0val(wih0, whh0, n1, k+8), w0val(wih0, whh0, n1, k+9));
        g_W0q[tid] = u;
    }
    if (tid < 16*KT1*64) {
        int q = tid & 1, r = tid >> 1;
        int lane = r & 31, r2 = r >> 5;
        int kt = r2 % KT1, jb = r2 / KT1;
        int k = kt*16 + (lane & 3)*2;
        int g0 = q*2, g1 = q*2 + 1;
        int n0 = g0*128 + jb*8 + (lane >> 2);
        int n1 = g1*128 + jb*8 + (lane >> 2);
        uint4 u;
        u.x = pack2(w1val(wih1, whh1, n0, k),   w1val(wih1, whh1, n0, k+1));
        u.y = pack2(w1val(wih1, whh1, n0, k+8), w1val(wih1, whh1, n0, k+9));
        u.z = pack2(w1val(wih1, whh1, n1, k),   w1val(wih1, whh1, n1, k+1));
        u.w = pack2(w1val(wih1, whh1, n1, k+8), w1val(wih1, whh1, n1, k+9));
        g_W1q[tid] = u;
    }
}

// ---------------------------------------------------------------------------
// Fused LSTM epilogue: acc[mt][gate][q] -> activations -> c update -> h stores
// sB: biases, 0.5-prescaled for i/f/o gates, raw for g.
// cW: per-warp c slice (16 cells x 32 lanes), conflict-free.
// ---------------------------------------------------------------------------
template<bool DUAL>
__device__ __forceinline__ void lstm_epilogue(
    float (&acc)[4][4][4], const float* __restrict__ sB, float* __restrict__ cW,
    int jb,
    half* __restrict__ dA, int strA, int offA,
    half* __restrict__ dB, int strB, int offB, int lane)
{
    const int j0 = jb*8 + (lane & 3)*2;
    const float2 bI = *(const float2*)&sB[        j0];
    const float2 bF = *(const float2*)&sB[128   + j0];
    const float2 bG = *(const float2*)&sB[256   + j0];
    const float2 bO = *(const float2*)&sB[384   + j0];
    const __half2 H05 = __float2half2_rn(0.5f);
#pragma unroll
    for (int mt = 0; mt < 4; ++mt) {
        const int r0 = mt*16 + (lane >> 2);
#pragma unroll
        for (int hq = 0; hq < 2; ++hq) {
            const int row = r0 + hq*8;
            const float aI0 = acc[mt][0][2*hq], aI1 = acc[mt][0][2*hq+1];
            const float aF0 = acc[mt][1][2*hq], aF1 = acc[mt][1][2*hq+1];
            const float aG0 = acc[mt][2][2*hq], aG1 = acc[mt][2][2*hq+1];
            const float aO0 = acc[mt][3][2*hq], aO1 = acc[mt][3][2*hq+1];
            // sigmoid(x) = 0.5*tanh(0.5x)+0.5 ; biases prescaled by 0.5 for i/f/o
            __half2 TI = lh2tanh(__floats2half2_rn(fmaf(aI0,0.5f,bI.x), fmaf(aI1,0.5f,bI.y)));
            __half2 TF = lh2tanh(__floats2half2_rn(fmaf(aF0,0.5f,bF.x), fmaf(aF1,0.5f,bF.y)));
            __half2 TG = lh2tanh(__floats2half2_rn(aG0 + bG.x,          aG1 + bG.y));
            __half2 TO = lh2tanh(__floats2half2_rn(fmaf(aO0,0.5f,bO.x), fmaf(aO1,0.5f,bO.y)));
            __half2 SI = __hfma2(TI, H05, H05);
            __half2 SF = __hfma2(TF, H05, H05);
            __half2 SO = __hfma2(TO, H05, H05);
            float2 fI = __half22float2(SI);
            float2 fF = __half22float2(SF);
            float2 fG = __half22float2(TG);
            const int ci = mt*4 + hq*2;
            float c0 = cW[ci*32 + lane];
            float c1 = cW[(ci+1)*32 + lane];
            c0 = fmaf(fF.x, c0, fI.x * fG.x);
            c1 = fmaf(fF.y, c1, fI.y * fG.y);
            cW[ci*32 + lane]     = c0;
            cW[(ci+1)*32 + lane] = c1;
            __half2 H = __hmul2(SO, lh2tanh(__floats2half2_rn(c0, c1)));
            *(__half2*)&dA[row*strA + offA + j0] = H;
            if (DUAL) *(__half2*)&dB[row*strB + offB + j0] = H;
        }
    }
}

// breg fill from two uint4 (gates 0..3)
__device__ __forceinline__ void bfill(uint32_t (&b)[4][2], uint4 v0, uint4 v1) {
    b[0][0] = v0.x; b[0][1] = v0.y;
    b[1][0] = v0.z; b[1][1] = v0.w;
    b[2][0] = v1.x; b[2][1] = v1.y;
    b[3][0] = v1.z; b[3][1] = v1.w;
}

// ---------------------------------------------------------------------------
// Single-layer GEMM (prologue L0(0) and tail L1(27)). Ring-3 B prefetch,
// internal __syncthreads after first prefetches.
// ---------------------------------------------------------------------------
template<int KT, int SAS, bool DUAL>
__device__ __forceinline__ void gemm_single(
    const half* sA, const uint4* __restrict__ Wq,
    const float* __restrict__ sB, float* __restrict__ cW,
    half* __restrict__ dA, int strA, int offA,
    half* __restrict__ dB, int strB, int offB,
    int warp, int lane)
{
    const uint32_t aBase = (uint32_t)__cvta_generic_to_shared(sA);
    const int lrow  = lane & 15;
    const int lkoff = (lane >> 4) * 8;
    const uint4* W = Wq + ((size_t)warp*KT*32 + lane)*2;

    uint32_t breg[3][4][2];
    uint32_t areg[4][4];
    float acc[4][4][4];

    auto loadB = [&](int kt) {
        const uint4* p = W + kt*64;
        bfill(breg[kt % 3], p[0], p[1]);
    };

    loadB(0); loadB(1);
    __syncthreads();               // covers producer writes of this phase

#pragma unroll
    for (int mt = 0; mt < 4; ++mt)
#pragma unroll
        for (int s = 0; s < 4; ++s)
#pragma unroll
            for (int q = 0; q < 4; ++q) acc[mt][s][q] = 0.0f;

#pragma unroll
    for (int kt = 0; kt < KT; ++kt) {
#pragma unroll
        for (int mt = 0; mt < 4; ++mt)
            ldsm4(areg[mt],
                  aBase + (uint32_t)(((mt*16 + lrow)*SAS + kt*16 + lkoff) * 2));
        if (kt + 2 < KT) loadB(kt + 2);
#pragma unroll
        for (int mt = 0; mt < 4; ++mt)
#pragma unroll
            for (int s = 0; s < 4; ++s)
                mma16816(acc[mt][s], areg[mt], breg[kt % 3][s]);
    }
    lstm_epilogue<DUAL>(acc, sB, cW, warp, dA, strA, offA, dB, strB, offB, lane);
}

// ---------------------------------------------------------------------------
// Fused phase {L1(t), L0(t+1)}: unified 26-kt stream, one barrier, L1 epilogue
// embedded mid-stream (no barrier), L0 epilogue at the end.
// ---------------------------------------------------------------------------
__device__ __forceinline__ void gemm_phase(
    const half* sA1, const half* sA0,
    half* __restrict__ a1w, half* __restrict__ a0w,
    const float* __restrict__ sB0, const float* __restrict__ sB1,
    float* __restrict__ c0W, float* __restrict__ c1W,
    int warp, int lane)
{
    const uint32_t aBase1 = (uint32_t)__cvta_generic_to_shared(sA1);
    const uint32_t aBase0 = (uint32_t)__cvta_generic_to_shared(sA0);
    const int lrow  = lane & 15;
    const int lkoff = (lane >> 4) * 8;
    const uint4* W1 = g_W1q + ((size_t)warp*KT1*32 + lane)*2;
    const uint4* W0 = g_W0q + ((size_t)warp*KT0*32 + lane)*2;

    uint32_t breg[3][4][2];
    uint32_t areg[4][4];
    float acc[4][4][4];

    auto loadB = [&](int u) {
        const uint4* p = (u < KT1) ? (W1 + u*64) : (W0 + (u - KT1)*64);
        bfill(breg[u % 3], p[0], p[1]);
    };

    loadB(0); loadB(1);
    __syncthreads();               // covers all producer writes of prev phase

#pragma unroll
    for (int mt = 0; mt < 4; ++mt)
#pragma unroll
        for (int s = 0; s < 4; ++s)
#pragma unroll
            for (int q = 0; q < 4; ++q) acc[mt][s][q] = 0.0f;

#pragma unroll
    for (int u = 0; u < KTP; ++u) {
        const int seg1 = (u < KT1);
        const int kt   = seg1 ? u : u - KT1;
        const uint32_t ab = seg1 ? aBase1 : aBase0;
        const int sas     = seg1 ? SA1_S  : SA0_S;
#pragma unroll
        for (int mt = 0; mt < 4; ++mt)
            ldsm4(areg[mt],
                  ab + (uint32_t)(((mt*16 + lrow)*sas + kt*16 + lkoff) * 2));
        if (u + 2 < KTP) loadB(u + 2);   // ring-3: (u+2)%3 aliases nothing live
#pragma unroll
        for (int mt = 0; mt < 4; ++mt)
#pragma unroll
            for (int s = 0; s < 4; ++s)
                mma16816(acc[mt][s], areg[mt], breg[u % 3][s]);
        if (u == KT1 - 1) {
            // L1(t) epilogue: h1(t) -> a1w cols 0..127 ; c1 update
            lstm_epilogue<false>(acc, sB1, c1W, warp,
                                 a1w, SA1_S, 0, (half*)0, 0, 0, lane);
#pragma unroll
            for (int mt = 0; mt < 4; ++mt)
#pragma unroll
                for (int s = 0; s < 4; ++s)
#pragma unroll
                    for (int q = 0; q < 4; ++q) acc[mt][s][q] = 0.0f;
        }
    }
    // L0(t+1) epilogue: h0(t+1) -> a0w cols 32.. and a1w cols 128.. ; c0 update
    lstm_epilogue<true>(acc, sB0, c0W, warp,
                        a0w, SA0_S, 32, a1w, SA1_S, 128, lane);
}

// ---------------------------------------------------------------------------
__global__ __launch_bounds__(NT, 1)
void lstm_kernel(const float* __restrict__ x, const float* __restrict__ w_out,
                 const float* __restrict__ b_out, float* __restrict__ out) {
    extern __shared__ char smem[];
    half*  A0 = (half*)(smem + OFF_A0);   // 2 buffers [64][168]: 0..31 x(+pad), 32..159 h0
    half*  A1 = (half*)(smem + OFF_A1);   // 2 buffers [64][264]: 0..127 h1, 128..255 h0
    float* C0 = (float*)(smem + OFF_C0);  // [warp][cell(16)][lane]
    float* C1 = (float*)(smem + OFF_C1);
    float* sB0 = (float*)(smem + OFF_B0);
    float* sB1 = (float*)(smem + OFF_B1);

    const int tid  = threadIdx.x;
    const int warp = tid >> 5;
    const int lane = tid & 31;
    float* c0W = C0 + warp*512;
    float* c1W = C1 + warp*512;

    // init: zero states + x pad, scaled biases
    for (int i = tid; i < 2*A0_HALVES; i += NT) ((unsigned short*)A0)[i] = 0;
    for (int i = tid; i < 2*A1_HALVES; i += NT) ((unsigned short*)A1)[i] = 0;
    for (int i = tid; i < 16*512; i += NT) { C0[i] = 0.0f; C1[i] = 0.0f; }
    for (int i = tid; i < GATES; i += NT) {
        float b0 = g_bias0[i], b1 = g_bias1[i];
        bool gg = ((i >> 7) == 2);
        sB0[i] = gg ? b0 : 0.5f*b0;
        sB1[i] = gg ? b1 : 0.5f*b1;
    }

    const float* xb = x + (size_t)blockIdx.x * BTILE * 784;

    half* a0r = A0;             half* a0w = A0 + A0_HALVES;
    half* a1r = A1;             half* a1w = A1 + A1_HALVES;

    // x(0) -> a0r ; stage x(1) -> a0w  (visibility: sync inside first gemm)
    for (int i = tid; i < BTILE*28; i += NT) {
        int r = i / 28, c = i - r*28;
        a0r[r*SA0_S + c] = __float2half(xb[(size_t)r*784 + 0*28 + c]);
        a0w[r*SA0_S + c] = __float2half(xb[(size_t)r*784 + 1*28 + c]);
    }

    // Prologue: L0(0): reads a0r=[x0|0]; h0(0) -> a0w cols32 AND a1r cols128
    gemm_single<KT0, SA0_S, true>(a0r, g_W0q, sB0, c0W,
                                  a0w, SA0_S, 32, a1r, SA1_S, 128, warp, lane);
    { half* tmp = a0r; a0r = a0w; a0w = tmp; }   // a0r = [x1 | h0(0)]

    // 27 fused phases: t = 0..26 runs {L1(t), L0(t+1)}
    for (int t = 0; t < TSTEPS - 1; ++t) {
        gemm_phase(a1r, a0r, a1w, a0w, sB0, sB1, c0W, c1W, warp, lane);
        // stage x(t+2) into a0w cols 0..27 (read after next phase barrier)
        if (t + 2 < TSTEPS) {
            for (int i = tid; i < BTILE*28; i += NT) {
                int r = i / 28, c = i - r*28;
                a0w[r*SA0_S + c] = __float2half(xb[(size_t)r*784 + (t+2)*28 + c]);
            }
        }
        half* tmp;
        tmp = a0r; a0r = a0w; a0w = tmp;
        tmp = a1r; a1r = a1w; a1w = tmp;
    }

    // Tail: L1(27): reads a1r=[h1(26)|h0(27)]; h1(27) -> a1w cols 0..127
    gemm_single<KT1, SA1_S, false>(a1r, g_W1q, sB1, c1W,
                                   a1w, SA1_S, 0, (half*)0, 0, 0, warp, lane);
    __syncthreads();

    // output head: out[n][o] = h1(27) . w_out[o] + b_out[o]
    const size_t ng0 = (size_t)blockIdx.x * BTILE;
    for (int i = tid; i < BTILE*10; i += NT) {
        int n = i / 10, o = i - n*10;
        float s = b_out[o];
        const half* hr = a1w + (size_t)n*SA1_S;
#pragma unroll 8
        for (int j = 0; j < HIDN; ++j)
            s = fmaf(__half2float(hr[j]), w_out[o*HIDN + j], s);
        out[(ng0 + n)*10 + o] = s;
    }
}

// ---------------------------------------------------------------------------
extern "C" void kernel_launch(void* const* d_in, const int* in_sizes, int n_in,
                              void* d_out, int out_size) {
    const float* x     = (const float*)d_in[0];
    const float* wih0  = (const float*)d_in[1];
    const float* whh0  = (const float*)d_in[2];
    const float* bih0  = (const float*)d_in[3];
    const float* bhh0  = (const float*)d_in[4];
    const float* wih1  = (const float*)d_in[5];
    const float* whh1  = (const float*)d_in[6];
    const float* bih1  = (const float*)d_in[7];
    const float* bhh1  = (const float*)d_in[8];
    const float* w_out = (const float*)d_in[9];
    const float* b_out = (const float*)d_in[10];

    cudaFuncSetAttribute(lstm_kernel, cudaFuncAttributeMaxDynamicSharedMemorySize, SMEM_BYTES);

    prep_kernel<<<128, 256>>>(wih0, whh0, bih0, bhh0, wih1, whh1, bih1, bhh1);
    lstm_kernel<<<NCTA, NT, SMEM_BYTES>>>(x, w_out, b_out, (float*)d_out);
}

// round 17
// speedup vs baseline: 1.0115x; 1.0031x over previous
#include <cuda_runtime.h>
#include <cuda_fp16.h>
#include <cstdint>

// ---------------------------------------------------------------------------
// Persistent fused 2-layer LSTM, fp16 tensor cores, FUSED cell update,
// CROSS-LAYER phase fusion: layer1(t) and layer0(t+1) are independent, so one
// barrier phase runs a unified 26-kt MMA stream {W1 | W0} with the L1 epilogue
// embedded mid-stream. Barriers: 2/step -> ~1/step. Weights as uint4 packs
// (2x LDG.128 per kt). 16 warps, warp = jb tile, mt=4 row tiles.
// ---------------------------------------------------------------------------

#define NT      512
#define BTILE   64
#define NCTA    128
#define TSTEPS  28
#define HIDN    128
#define GATES   512
#define KT0     10          // K=160 (32-padded x | h0) / 16
#define KT1     16          // K=256 (h1 | h0) / 16
#define KTP     (KT1+KT0)   // 26: unified phase stream
#define SA0_S   168         // halves per row
#define SA1_S   264

#define A0_HALVES (64*SA0_S)                 // 10752 per buffer
#define A1_HALVES (64*SA1_S)                 // 16896 per buffer

#define OFF_A0   0
#define OFF_A1   (OFF_A0 + 2*A0_HALVES*2)    // 43008
#define OFF_C0   (OFF_A1 + 2*A1_HALVES*2)    // 110592
#define OFF_C1   (OFF_C0 + 16*512*4)         // 143360
#define OFF_B0   (OFF_C1 + 16*512*4)         // 176128
#define OFF_B1   (OFF_B0 + GATES*4)          // 178176
#define SMEM_BYTES (OFF_B1 + GATES*4)        // 180224

// uint4-packed weights: [jb(16)][kt][lane(32)][2]; q=0 -> gates 0,1 ; q=1 -> 2,3
__device__ __align__(16) uint4 g_W0q[16*KT0*64];
__device__ __align__(16) uint4 g_W1q[16*KT1*64];
__device__ float g_bias0[GATES];
__device__ float g_bias1[GATES];

// ---------------------------------------------------------------------------
__device__ __forceinline__ __half2 lh2tanh(__half2 x) {
    __half2 y;
    asm("tanh.approx.f16x2 %0, %1;" : "=r"(*(uint32_t*)&y) : "r"(*(uint32_t*)&x));
    return y;
}

__device__ __forceinline__ void ldsm4(uint32_t* r, uint32_t addr) {
    asm volatile("ldmatrix.sync.aligned.m8n8.x4.shared.b16 {%0,%1,%2,%3}, [%4];"
                 : "=r"(r[0]), "=r"(r[1]), "=r"(r[2]), "=r"(r[3]) : "r"(addr));
}

__device__ __forceinline__ void mma16816(float* c, const uint32_t* a, const uint32_t* b) {
    asm volatile("mma.sync.aligned.m16n8k16.row.col.f32.f16.f16.f32 "
                 "{%0,%1,%2,%3}, {%4,%5,%6,%7}, {%8,%9}, {%0,%1,%2,%3};"
                 : "+f"(c[0]), "+f"(c[1]), "+f"(c[2]), "+f"(c[3])
                 : "r"(a[0]), "r"(a[1]), "r"(a[2]), "r"(a[3]), "r"(b[0]), "r"(b[1]));
}

__device__ __forceinline__ uint32_t pack2(float a, float b) {
    __half2 h = __floats2half2_rn(a, b);
    return *reinterpret_cast<uint32_t*>(&h);
}

// ---------------------------------------------------------------------------
// Prep: pack weights into gate-major uint4 fragment layout + fuse biases.
// Column n = gate*128 + jb*8 + (lane>>2); k = kt*16 + (lane&3)*2.
// W0[n][k]: k<28 -> w_ih0, 28..31 -> 0, 32..159 -> w_hh0[k-32]
// W1[n][k]: k<128 -> w_hh1, else w_ih1[k-128]
// ---------------------------------------------------------------------------
__device__ __forceinline__ float w0val(const float* wih0, const float* whh0, int n, int k) {
    if (k < 28)  return wih0[n*28 + k];
    if (k < 32)  return 0.0f;
    return whh0[n*HIDN + (k - 32)];
}
__device__ __forceinline__ float w1val(const float* wih1, const float* whh1, int n, int k) {
    if (k < HIDN) return whh1[n*HIDN + k];
    return wih1[n*HIDN + (k - HIDN)];
}

__global__ void prep_kernel(const float* __restrict__ wih0, const float* __restrict__ whh0,
                            const float* __restrict__ bih0, const float* __restrict__ bhh0,
                            const float* __restrict__ wih1, const float* __restrict__ whh1,
                            const float* __restrict__ bih1, const float* __restrict__ bhh1) {
    int tid = blockIdx.x * blockDim.x + threadIdx.x;
    if (tid < GATES) {
        g_bias0[tid] = bih0[tid] + bhh0[tid];
        g_bias1[tid] = bih1[tid] + bhh1[tid];
    }
    if (tid < 16*KT0*64) {
        int q = tid & 1, r = tid >> 1;
        int lane = r & 31, r2 = r >> 5;
        int kt = r2 % KT0, jb = r2 / KT0;
        int k = kt*16 + (lane & 3)*2;
        int g0 = q*2, g1 = q*2 + 1;
        int n0 = g0*128 + jb*8 + (lane >> 2);
        int n1 = g1*128 + jb*8 + (lane >> 2);
        uint4 u;
        u.x = pack2(w0val(wih0, whh0, n0, k),   w0val(wih0, whh0, n0, k+1));
        u.y = pack2(w0val(wih0, whh0, n0, k+8), w0val(wih0, whh0, n0, k+9));
        u.z = pack2(w0val(wih0, whh0, n1, k),   w0val(wih0, whh0, n1, k+1));
        u.w = pack2(w0val(wih0, whh0, n1, k+8), w0val(wih0, whh0, n1, k+9));
        g_W0q[tid] = u;
    }
    if (tid < 16*KT1*64) {
        int q = tid & 1, r = tid >> 1;
        int lane = r & 31, r2 = r >> 5;
        int kt = r2 % KT1, jb = r2 / KT1;
        int k = kt*16 + (lane & 3)*2;
        int g0 = q*2, g1 = q*2 + 1;
        int n0 = g0*128 + jb*8 + (lane >> 2);
        int n1 = g1*128 + jb*8 + (lane >> 2);
        uint4 u;
        u.x = pack2(w1val(wih1, whh1, n0, k),   w1val(wih1, whh1, n0, k+1));
        u.y = pack2(w1val(wih1, whh1, n0, k+8), w1val(wih1, whh1, n0, k+9));
        u.z = pack2(w1val(wih1, whh1, n1, k),   w1val(wih1, whh1, n1, k+1));
        u.w = pack2(w1val(wih1, whh1, n1, k+8), w1val(wih1, whh1, n1, k+9));
        g_W1q[tid] = u;
    }
}

// ---------------------------------------------------------------------------
// Fused LSTM epilogue: acc[mt][gate][q] -> activations -> c update -> h stores
// sB: biases, 0.5-prescaled for i/f/o gates, raw for g.
// cW: per-warp c slice (16 cells x 32 lanes), conflict-free.
// ---------------------------------------------------------------------------
template<bool DUAL>
__device__ __forceinline__ void lstm_epilogue(
    float (&acc)[4][4][4], const float* __restrict__ sB, float* __restrict__ cW,
    int jb,
    half* __restrict__ dA, int strA, int offA,
    half* __restrict__ dB, int strB, int offB, int lane)
{
    const int j0 = jb*8 + (lane & 3)*2;
    const float2 bI = *(const float2*)&sB[        j0];
    const float2 bF = *(const float2*)&sB[128   + j0];
    const float2 bG = *(const float2*)&sB[256   + j0];
    const float2 bO = *(const float2*)&sB[384   + j0];
    const __half2 H05 = __float2half2_rn(0.5f);
#pragma unroll
    for (int mt = 0; mt < 4; ++mt) {
        const int r0 = mt*16 + (lane >> 2);
#pragma unroll
        for (int hq = 0; hq < 2; ++hq) {
            const int row = r0 + hq*8;
            const float aI0 = acc[mt][0][2*hq], aI1 = acc[mt][0][2*hq+1];
            const float aF0 = acc[mt][1][2*hq], aF1 = acc[mt][1][2*hq+1];
            const float aG0 = acc[mt][2][2*hq], aG1 = acc[mt][2][2*hq+1];
            const float aO0 = acc[mt][3][2*hq], aO1 = acc[mt][3][2*hq+1];
            // sigmoid(x) = 0.5*tanh(0.5x)+0.5 ; biases prescaled by 0.5 for i/f/o
            __half2 TI = lh2tanh(__floats2half2_rn(fmaf(aI0,0.5f,bI.x), fmaf(aI1,0.5f,bI.y)));
            __half2 TF = lh2tanh(__floats2half2_rn(fmaf(aF0,0.5f,bF.x), fmaf(aF1,0.5f,bF.y)));
            __half2 TG = lh2tanh(__floats2half2_rn(aG0 + bG.x,          aG1 + bG.y));
            __half2 TO = lh2tanh(__floats2half2_rn(fmaf(aO0,0.5f,bO.x), fmaf(aO1,0.5f,bO.y)));
            __half2 SI = __hfma2(TI, H05, H05);
            __half2 SF = __hfma2(TF, H05, H05);
            __half2 SO = __hfma2(TO, H05, H05);
            float2 fI = __half22float2(SI);
            float2 fF = __half22float2(SF);
            float2 fG = __half22float2(TG);
            const int ci = mt*4 + hq*2;
            float c0 = cW[ci*32 + lane];
            float c1 = cW[(ci+1)*32 + lane];
            c0 = fmaf(fF.x, c0, fI.x * fG.x);
            c1 = fmaf(fF.y, c1, fI.y * fG.y);
            cW[ci*32 + lane]     = c0;
            cW[(ci+1)*32 + lane] = c1;
            __half2 H = __hmul2(SO, lh2tanh(__floats2half2_rn(c0, c1)));
            *(__half2*)&dA[row*strA + offA + j0] = H;
            if (DUAL) *(__half2*)&dB[row*strB + offB + j0] = H;
        }
    }
}

// breg fill from two uint4 (gates 0..3)
__device__ __forceinline__ void bfill(uint32_t (&b)[4][2], uint4 v0, uint4 v1) {
    b[0][0] = v0.x; b[0][1] = v0.y;
    b[1][0] = v0.z; b[1][1] = v0.w;
    b[2][0] = v1.x; b[2][1] = v1.y;
    b[3][0] = v1.z; b[3][1] = v1.w;
}

// ---------------------------------------------------------------------------
// Single-layer GEMM (prologue L0(0) and tail L1(27)). Ring-3 B prefetch,
// internal __syncthreads after first prefetches.
// ---------------------------------------------------------------------------
template<int KT, int SAS, bool DUAL>
__device__ __forceinline__ void gemm_single(
    const half* sA, const uint4* __restrict__ Wq,
    const float* __restrict__ sB, float* __restrict__ cW,
    half* __restrict__ dA, int strA, int offA,
    half* __restrict__ dB, int strB, int offB,
    int warp, int lane)
{
    const uint32_t aBase = (uint32_t)__cvta_generic_to_shared(sA);
    const int lrow  = lane & 15;
    const int lkoff = (lane >> 4) * 8;
    const uint4* W = Wq + ((size_t)warp*KT*32 + lane)*2;

    uint32_t breg[3][4][2];
    uint32_t areg[4][4];
    float acc[4][4][4];

    auto loadB = [&](int kt) {
        const uint4* p = W + kt*64;
        bfill(breg[kt % 3], p[0], p[1]);
    };

    loadB(0); loadB(1);
    __syncthreads();               // covers producer writes of this phase

#pragma unroll
    for (int mt = 0; mt < 4; ++mt)
#pragma unroll
        for (int s = 0; s < 4; ++s)
#pragma unroll
            for (int q = 0; q < 4; ++q) acc[mt][s][q] = 0.0f;

#pragma unroll
    for (int kt = 0; kt < KT; ++kt) {
#pragma unroll
        for (int mt = 0; mt < 4; ++mt)
            ldsm4(areg[mt],
                  aBase + (uint32_t)(((mt*16 + lrow)*SAS + kt*16 + lkoff) * 2));
        if (kt + 2 < KT) loadB(kt + 2);
#pragma unroll
        for (int mt = 0; mt < 4; ++mt)
#pragma unroll
            for (int s = 0; s < 4; ++s)
                mma16816(acc[mt][s], areg[mt], breg[kt % 3][s]);
    }
    lstm_epilogue<DUAL>(acc, sB, cW, warp, dA, strA, offA, dB, strB, offB, lane);
}

// ---------------------------------------------------------------------------
// Fused phase {L1(t), L0(t+1)}: unified 26-kt stream, one barrier, L1 epilogue
// embedded mid-stream (no barrier), L0 epilogue at the end.
// ---------------------------------------------------------------------------
__device__ __forceinline__ void gemm_phase(
    const half* sA1, const half* sA0,
    half* __restrict__ a1w, half* __restrict__ a0w,
    const float* __restrict__ sB0, const float* __restrict__ sB1,
    float* __restrict__ c0W, float* __restrict__ c1W,
    int warp, int lane)
{
    const uint32_t aBase1 = (uint32_t)__cvta_generic_to_shared(sA1);
    const uint32_t aBase0 = (uint32_t)__cvta_generic_to_shared(sA0);
    const int lrow  = lane & 15;
    const int lkoff = (lane >> 4) * 8;
    const uint4* W1 = g_W1q + ((size_t)warp*KT1*32 + lane)*2;
    const uint4* W0 = g_W0q + ((size_t)warp*KT0*32 + lane)*2;

    uint32_t breg[3][4][2];
    uint32_t areg[4][4];
    float acc[4][4][4];

    auto loadB = [&](int u) {
        const uint4* p = (u < KT1) ? (W1 + u*64) : (W0 + (u - KT1)*64);
        bfill(breg[u % 3], p[0], p[1]);
    };

    loadB(0); loadB(1);
    __syncthreads();               // covers all producer writes of prev phase

#pragma unroll
    for (int mt = 0; mt < 4; ++mt)
#pragma unroll
        for (int s = 0; s < 4; ++s)
#pragma unroll
            for (int q = 0; q < 4; ++q) acc[mt][s][q] = 0.0f;

#pragma unroll
    for (int u = 0; u < KTP; ++u) {
        const int seg1 = (u < KT1);
        const int kt   = seg1 ? u : u - KT1;
        const uint32_t ab = seg1 ? aBase1 : aBase0;
        const int sas     = seg1 ? SA1_S  : SA0_S;
#pragma unroll
        for (int mt = 0; mt < 4; ++mt)
            ldsm4(areg[mt],
                  ab + (uint32_t)(((mt*16 + lrow)*sas + kt*16 + lkoff) * 2));
        if (u + 2 < KTP) loadB(u + 2);   // ring-3: (u+2)%3 aliases nothing live
#pragma unroll
        for (int mt = 0; mt < 4; ++mt)
#pragma unroll
            for (int s = 0; s < 4; ++s)
                mma16816(acc[mt][s], areg[mt], breg[u % 3][s]);
        if (u == KT1 - 1) {
            // L1(t) epilogue: h1(t) -> a1w cols 0..127 ; c1 update
            lstm_epilogue<false>(acc, sB1, c1W, warp,
                                 a1w, SA1_S, 0, (half*)0, 0, 0, lane);
#pragma unroll
            for (int mt = 0; mt < 4; ++mt)
#pragma unroll
                for (int s = 0; s < 4; ++s)
#pragma unroll
                    for (int q = 0; q < 4; ++q) acc[mt][s][q] = 0.0f;
        }
    }
    // L0(t+1) epilogue: h0(t+1) -> a0w cols 32.. and a1w cols 128.. ; c0 update
    lstm_epilogue<true>(acc, sB0, c0W, warp,
                        a0w, SA0_S, 32, a1w, SA1_S, 128, lane);
}

// ---------------------------------------------------------------------------
__global__ __launch_bounds__(NT, 1)
void lstm_kernel(const float* __restrict__ x, const float* __restrict__ w_out,
                 const float* __restrict__ b_out, float* __restrict__ out) {
    extern __shared__ char smem[];
    half*  A0 = (half*)(smem + OFF_A0);   // 2 buffers [64][168]: 0..31 x(+pad), 32..159 h0
    half*  A1 = (half*)(smem + OFF_A1);   // 2 buffers [64][264]: 0..127 h1, 128..255 h0
    float* C0 = (float*)(smem + OFF_C0);  // [warp][cell(16)][lane]
    float* C1 = (float*)(smem + OFF_C1);
    float* sB0 = (float*)(smem + OFF_B0);
    float* sB1 = (float*)(smem + OFF_B1);

    const int tid  = threadIdx.x;
    const int warp = tid >> 5;
    const int lane = tid & 31;
    float* c0W = C0 + warp*512;
    float* c1W = C1 + warp*512;

    // init: zero states + x pad, scaled biases
    for (int i = tid; i < 2*A0_HALVES; i += NT) ((unsigned short*)A0)[i] = 0;
    for (int i = tid; i < 2*A1_HALVES; i += NT) ((unsigned short*)A1)[i] = 0;
    for (int i = tid; i < 16*512; i += NT) { C0[i] = 0.0f; C1[i] = 0.0f; }
    for (int i = tid; i < GATES; i += NT) {
        float b0 = g_bias0[i], b1 = g_bias1[i];
        bool gg = ((i >> 7) == 2);
        sB0[i] = gg ? b0 : 0.5f*b0;
        sB1[i] = gg ? b1 : 0.5f*b1;
    }

    const float* xb = x + (size_t)blockIdx.x * BTILE * 784;

    half* a0r = A0;             half* a0w = A0 + A0_HALVES;
    half* a1r = A1;             half* a1w = A1 + A1_HALVES;

    // x(0) -> a0r ; stage x(1) -> a0w  (visibility: sync inside first gemm)
    for (int i = tid; i < BTILE*28; i += NT) {
        int r = i / 28, c = i - r*28;
        a0r[r*SA0_S + c] = __float2half(xb[(size_t)r*784 + 0*28 + c]);
        a0w[r*SA0_S + c] = __float2half(xb[(size_t)r*784 + 1*28 + c]);
    }

    // Prologue: L0(0): reads a0r=[x0|0]; h0(0) -> a0w cols32 AND a1r cols128
    gemm_single<KT0, SA0_S, true>(a0r, g_W0q, sB0, c0W,
                                  a0w, SA0_S, 32, a1r, SA1_S, 128, warp, lane);
    { half* tmp = a0r; a0r = a0w; a0w = tmp; }   // a0r = [x1 | h0(0)]

    // 27 fused phases: t = 0..26 runs {L1(t), L0(t+1)}
    for (int t = 0; t < TSTEPS - 1; ++t) {
        gemm_phase(a1r, a0r, a1w, a0w, sB0, sB1, c0W, c1W, warp, lane);
        // stage x(t+2) into a0w cols 0..27 (read after next phase barrier)
        if (t + 2 < TSTEPS) {
            for (int i = tid; i < BTILE*28; i += NT) {
                int r = i / 28, c = i - r*28;
                a0w[r*SA0_S + c] = __float2half(xb[(size_t)r*784 + (t+2)*28 + c]);
            }
        }
        half* tmp;
        tmp = a0r; a0r = a0w; a0w = tmp;
        tmp = a1r; a1r = a1w; a1w = tmp;
    }

    // Tail: L1(27): reads a1r=[h1(26)|h0(27)]; h1(27) -> a1w cols 0..127
    gemm_single<KT1, SA1_S, false>(a1r, g_W1q, sB1, c1W,
                                   a1w, SA1_S, 0, (half*)0, 0, 0, warp, lane);
    __syncthreads();

    // output head: out[n][o] = h1(27) . w_out[o] + b_out[o]
    const size_t ng0 = (size_t)blockIdx.x * BTILE;
    for (int i = tid; i < BTILE*10; i += NT) {
        int n = i / 10, o = i - n*10;
        float s = b_out[o];
        const half* hr = a1w + (size_t)n*SA1_S;
#pragma unroll 8
        for (int j = 0; j < HIDN; ++j)
            s = fmaf(__half2float(hr[j]), w_out[o*HIDN + j], s);
        out[(ng0 + n)*10 + o] = s;
    }
}

// ---------------------------------------------------------------------------
extern "C" void kernel_launch(void* const* d_in, const int* in_sizes, int n_in,
                              void* d_out, int out_size) {
    const float* x     = (const float*)d_in[0];
    const float* wih0  = (const float*)d_in[1];
    const float* whh0  = (const float*)d_in[2];
    const float* bih0  = (const float*)d_in[3];
    const float* bhh0  = (const float*)d_in[4];
    const float* wih1  = (const float*)d_in[5];
    const float* whh1  = (const float*)d_in[6];
    const float* bih1  = (const float*)d_in[7];
    const float* bhh1  = (const float*)d_in[8];
    const float* w_out = (const float*)d_in[9];
    const float* b_out = (const float*)d_in[10];

    cudaFuncSetAttribute(lstm_kernel, cudaFuncAttributeMaxDynamicSharedMemorySize, SMEM_BYTES);

    prep_kernel<<<128, 256>>>(wih0, whh0, bih0, bhh0, wih1, whh1, bih1, bhh1);
    lstm_kernel<<<NCTA, NT, SMEM_BYTES>>>(x, w_out, b_out, (float*)d_out);
}